// round 14
// baseline (speedup 1.0000x reference)
#include <cuda_runtime.h>
#include <cuda_fp16.h>
#include <math.h>

#define BB 2
#define SS 2048
#define HH 16
#define DD 64
#define DIM 1024
#define MROWS (BB*SS)

// fp16 staging (device globals; no allocs allowed)
__device__ __align__(16) __half g_x16[MROWS*DIM];
__device__ __align__(16) __half g_Wq16[DIM*DIM];
__device__ __align__(16) __half g_Wk16[DIM*DIM];
__device__ __align__(16) __half g_Wv16[DIM*DIM];
__device__ __align__(16) __half g_Wo16[DIM*DIM];
__device__ __align__(16) __half g_Q16[BB*HH*SS*DD];   // (B,H,S,D), PRE-SCALED by 0.125*log2(e)
__device__ __align__(16) __half g_K16[BB*HH*SS*DD];
__device__ __align__(16) __half g_V16[BB*HH*SS*DD];
__device__ __align__(16) __half g_O16[MROWS*DIM];     // (B,S,H*D)

// ---------------- helpers ----------------
__device__ __forceinline__ void cp16(void* s, const void* g) {
    unsigned saddr = (unsigned)__cvta_generic_to_shared(s);
    asm volatile("cp.async.cg.shared.global [%0], [%1], 16;\n" :: "r"(saddr), "l"(g));
}
__device__ __forceinline__ void cp_commit() { asm volatile("cp.async.commit_group;\n"); }
template<int N> __device__ __forceinline__ void cp_wait() {
    asm volatile("cp.async.wait_group %0;\n" :: "n"(N));
}
__device__ __forceinline__ float ex2f(float x) {           // single EX2 (MUFU)
    float r;
    asm("ex2.approx.f32 %0, %1;" : "=f"(r) : "f"(x));
    return r;
}

__global__ __launch_bounds__(256) void f2h_kernel(const float2* __restrict__ src,
                                                  __half2* __restrict__ dst, int n2) {
    int i = blockIdx.x * blockDim.x + threadIdx.x;
    if (i < n2) { float2 v = src[i]; dst[i] = __floats2half2_rn(v.x, v.y); }
}

__global__ __launch_bounds__(256) void f2hW_kernel(
    const float2* __restrict__ Wq, const float2* __restrict__ Wk,
    const float2* __restrict__ Wv, const float2* __restrict__ Wo)
{
    const float2* src;
    __half2* dst;
    if (blockIdx.z == 0)      { src = Wq; dst = (__half2*)g_Wq16; }
    else if (blockIdx.z == 1) { src = Wk; dst = (__half2*)g_Wk16; }
    else if (blockIdx.z == 2) { src = Wv; dst = (__half2*)g_Wv16; }
    else                      { src = Wo; dst = (__half2*)g_Wo16; }
    int i = blockIdx.x * blockDim.x + threadIdx.x;
    float2 v = src[i];
    dst[i] = __floats2half2_rn(v.x, v.y);
}

// ---------------- mma / ldmatrix PTX ----------------
__device__ __forceinline__ void ldsm4(unsigned& r0, unsigned& r1, unsigned& r2, unsigned& r3, unsigned addr) {
    asm volatile("ldmatrix.sync.aligned.m8n8.x4.shared.b16 {%0,%1,%2,%3}, [%4];\n"
                 : "=r"(r0), "=r"(r1), "=r"(r2), "=r"(r3) : "r"(addr));
}
__device__ __forceinline__ void ldsm4t(unsigned& r0, unsigned& r1, unsigned& r2, unsigned& r3, unsigned addr) {
    asm volatile("ldmatrix.sync.aligned.m8n8.x4.trans.shared.b16 {%0,%1,%2,%3}, [%4];\n"
                 : "=r"(r0), "=r"(r1), "=r"(r2), "=r"(r3) : "r"(addr));
}
__device__ __forceinline__ void mma16816(float* c, const unsigned* a, const unsigned* b) {
    asm volatile("mma.sync.aligned.m16n8k16.row.col.f32.f16.f16.f32 "
                 "{%0,%1,%2,%3}, {%4,%5,%6,%7}, {%8,%9}, {%0,%1,%2,%3};\n"
                 : "+f"(c[0]), "+f"(c[1]), "+f"(c[2]), "+f"(c[3])
                 : "r"(a[0]), "r"(a[1]), "r"(a[2]), "r"(a[3]), "r"(b[0]), "r"(b[1]));
}

// ---------------------------------------------------------------------------
// Projection GEMM (raw mma): 128x128 tile, 256 threads (8 warps, 4x2 grid),
// warp tile 32x64. KC=64, 3-stage cp.async, ONE barrier per chunk,
// register-direct epilogue.
// ---------------------------------------------------------------------------
#define PLA 72
#define PLB 136
#define KC  64
#define NSTG 3
#define A_ST_BYTES (128*PLA*2)     // 18432
#define B_ST_BYTES (KC*PLB*2)      // 17408
#define PROJ_SMEM (NSTG*A_ST_BYTES + NSTG*B_ST_BYTES)   // 107520

struct ProjC { float c[2][8][4]; };

__device__ __forceinline__ void proj_issue(const __half* __restrict__ X,
                                           const __half* __restrict__ W,
                                           char* smem, int m0, int n0, int k0,
                                           int buf, int tid)
{
    __half* As = (__half*)(smem + buf * A_ST_BYTES);
    __half* Bs = (__half*)(smem + NSTG * A_ST_BYTES + buf * B_ST_BYTES);
#pragma unroll
    for (int i = tid; i < 1024; i += 256) {
        int r = i >> 3, c = (i & 7) << 3;
        cp16(As + r*PLA + c, X + (size_t)(m0 + r)*DIM + k0 + c);
    }
#pragma unroll
    for (int i = tid; i < 1024; i += 256) {
        int r = i >> 4, c = (i & 15) << 3;
        cp16(Bs + r*PLB + c, W + (size_t)(k0 + r)*DIM + n0 + c);
    }
}

__device__ __forceinline__ void proj_mainloop_raw(
    const __half* __restrict__ X, const __half* __restrict__ W,
    int m0, int n0, char* smem, int tid, ProjC& P)
{
    const int wid = tid >> 5, lane = tid & 31;
    const int wm = wid >> 1, wn = wid & 1;
    const int l8 = lane & 7, g = lane >> 3;
    const int a_row = (g & 1) * 8 + l8, a_col = (g >> 1) * 8;
    const int b_row = (g & 1) * 8 + l8, b_col = (g >> 1) * 8;

#pragma unroll
    for (int i = 0; i < 2; i++)
#pragma unroll
        for (int j = 0; j < 8; j++)
#pragma unroll
            for (int t = 0; t < 4; t++) P.c[i][j][t] = 0.f;

    const unsigned smem_u = (unsigned)__cvta_generic_to_shared(smem);

    proj_issue(X, W, smem, m0, n0, 0, 0, tid); cp_commit();
    proj_issue(X, W, smem, m0, n0, KC, 1, tid); cp_commit();

    const int NIT = DIM / KC;
    for (int it = 0; it < NIT; it++) {
        int buf = it % NSTG;
        if (it + 1 < NIT) cp_wait<1>(); else cp_wait<0>();
        __syncthreads();
        if (it + 2 < NIT) { proj_issue(X, W, smem, m0, n0, (it + 2) * KC, (it + 2) % NSTG, tid); cp_commit(); }

        unsigned as_base = smem_u + buf * A_ST_BYTES;
        unsigned bs_base = smem_u + NSTG * A_ST_BYTES + buf * B_ST_BYTES;

#pragma unroll
        for (int kk = 0; kk < KC/16; kk++) {
            unsigned af[2][4];
#pragma unroll
            for (int i = 0; i < 2; i++)
                ldsm4(af[i][0], af[i][1], af[i][2], af[i][3],
                      as_base + (unsigned)(((wm*32 + i*16 + a_row)*PLA + kk*16 + a_col) * 2));
#pragma unroll
            for (int ng = 0; ng < 4; ng++) {
                unsigned br[4];
                ldsm4t(br[0], br[1], br[2], br[3],
                       bs_base + (unsigned)(((kk*16 + b_row)*PLB + wn*64 + ng*16 + b_col) * 2));
                mma16816(P.c[0][2*ng],   af[0], br);
                mma16816(P.c[0][2*ng+1], af[0], br + 2);
                mma16816(P.c[1][2*ng],   af[1], br);
                mma16816(P.c[1][2*ng+1], af[1], br + 2);
            }
        }
    }
}

__global__ __launch_bounds__(256,2) void qkv16_kernel()
{
    extern __shared__ __align__(16) char smem[];

    const __half* W; __half* out;
    if (blockIdx.z == 0)      { W = g_Wq16; out = g_Q16; }
    else if (blockIdx.z == 1) { W = g_Wk16; out = g_K16; }
    else                      { W = g_Wv16; out = g_V16; }
    // Q gets 0.125 * log2(e): softmax runs in log2 domain (p = 2^(s'-m')).
    const float fscale = (blockIdx.z == 0) ? 0.18033688011118324f : 1.0f;

    const int tid = threadIdx.x, wid = tid >> 5, lane = tid & 31;
    const int wm = wid >> 1, wn = wid & 1;
    const int quad = lane >> 2, ql = lane & 3;
    const int m0 = blockIdx.y * 128, n0 = blockIdx.x * 128;

    ProjC P;
    proj_mainloop_raw(g_x16, W, m0, n0, smem, tid, P);

    const int bb = m0 >> 11, s0 = m0 & 2047;
    const int h = (n0 >> 6) + wn;
    __half* hb = out + (size_t)((bb << 4) + h) * SS * DD;
#pragma unroll
    for (int i = 0; i < 2; i++) {
        int ra = s0 + wm*32 + i*16 + quad;
        __half* pa_ = hb + (size_t)ra * DD;
        __half* pb_ = pa_ + 8 * DD;
#pragma unroll
        for (int j = 0; j < 8; j++) {
            int cc = j*8 + ql*2;
            *(__half2*)(pa_ + cc) = __floats2half2_rn(P.c[i][j][0]*fscale, P.c[i][j][1]*fscale);
            *(__half2*)(pb_ + cc) = __floats2half2_rn(P.c[i][j][2]*fscale, P.c[i][j][3]*fscale);
        }
    }
}

__global__ __launch_bounds__(256,2) void oproj16_kernel(float* __restrict__ C)
{
    extern __shared__ __align__(16) char smem[];
    const int tid = threadIdx.x, wid = tid >> 5, lane = tid & 31;
    const int wm = wid >> 1, wn = wid & 1;
    const int quad = lane >> 2, ql = lane & 3;
    const int m0 = blockIdx.y * 128, n0 = blockIdx.x * 128;

    ProjC P;
    proj_mainloop_raw(g_O16, g_Wo16, m0, n0, smem, tid, P);

#pragma unroll
    for (int i = 0; i < 2; i++) {
        float* pa_ = C + (size_t)(m0 + wm*32 + i*16 + quad) * DIM + n0 + wn*64;
        float* pb_ = pa_ + 8 * DIM;
#pragma unroll
        for (int j = 0; j < 8; j++) {
            int cc = j*8 + ql*2;
            *(float2*)(pa_ + cc) = make_float2(P.c[i][j][0], P.c[i][j][1]);
            *(float2*)(pb_ + cc) = make_float2(P.c[i][j][2], P.c[i][j][3]);
        }
    }
}

// ---------------------------------------------------------------------------
// Attention: register-resident FMHA, BQ=128, 8 warps, 4 KV buffers,
// 2 blocks per barrier. log2-domain softmax (Q pre-scaled by 0.125*log2e):
//   p = 2^(s'-m'), alpha = 2^(m'_old - m'_new)  -- exactly exp-domain math.
// Row sums come FREE from an extra ones-MMA (no shfl reduction).
// Division folded: u_j = (alpha_j/l_{j-1}) u_{j-1} + P_j V_j;  o = u_N / l_N.
// ---------------------------------------------------------------------------
#define LDH 72
#define A_QS   0
#define A_KS   18432
#define A_VS   (18432 + 4*9216)
#define ATT_SMEM (18432 + 8*9216)          // 92160

__global__ __launch_bounds__(256,2) void attn_reg_kernel()
{
    extern __shared__ __align__(16) char smem[];
    __half* Qs = (__half*)(smem + A_QS);

    const int tid = threadIdx.x, wid = tid >> 5, lane = tid & 31;
    const int qb = blockIdx.x, h = blockIdx.y, b = blockIdx.z;
    const int r0 = wid * 16;
    const int l8 = lane & 7, g = lane >> 3;
    const int quad = lane >> 2, ql = lane & 3;

    const __half* Qg  = g_Q16 + ((size_t)((b << 4) + h) * SS + qb * 128) * DD;
    const __half* Kg0 = g_K16 + (size_t)((b << 4) + h) * SS * DD;
    const __half* Vg0 = g_V16 + (size_t)((b << 4) + h) * SS * DD;

    auto issueKV = [&](int j) {
        int buf = j & 3;
        __half* Ks = (__half*)(smem + A_KS + buf * 9216);
        __half* Vs = (__half*)(smem + A_VS + buf * 9216);
        const __half* Kg = Kg0 + (size_t)j * (64*DD);
        const __half* Vg = Vg0 + (size_t)j * (64*DD);
#pragma unroll
        for (int i = tid; i < 512; i += 256) {
            int r = i >> 3, c = (i & 7) << 3;
            cp16(Ks + r*LDH + c, Kg + r*DD + c);
            cp16(Vs + r*LDH + c, Vg + r*DD + c);
        }
    };

    issueKV(0); issueKV(1); cp_commit();

#pragma unroll
    for (int i = tid; i < 1024; i += 256) {
        int r = i >> 3, c = (i & 7) << 3;
        *(uint4*)(Qs + r*LDH + c) = *(const uint4*)(Qg + r*DD + c);
    }
    __syncthreads();

    unsigned qs_base = (unsigned)__cvta_generic_to_shared(Qs);
    unsigned qf[4][4];
    {
        int qrow = r0 + (g & 1) * 8 + l8;
        int qcol = (g >> 1) * 8;
#pragma unroll
        for (int kt = 0; kt < 4; kt++) {
            ldsm4(qf[kt][0], qf[kt][1], qf[kt][2], qf[kt][3],
                  qs_base + (qrow*LDH + kt*16 + qcol) * 2);
        }
    }

    const int k_row = (g >> 1) * 8 + l8, k_col = (g & 1) * 8;
    const int v_row = (g & 1) * 8 + l8,  v_col = (g >> 1) * 8;
    const unsigned smem_base = (unsigned)__cvta_generic_to_shared(smem);
    const unsigned ones2 = 0x3C003C00u;               // half2(1.0, 1.0)
    const unsigned ones_b[2] = { ones2, ones2 };

    float u[8][4];
#pragma unroll
    for (int nt = 0; nt < 8; nt++) {
#pragma unroll
        for (int t = 0; t < 4; t++) u[nt][t] = 0.f;
    }

    float mrun_a = -INFINITY, mrun_b = -INFINITY, lrun_a = 0.f, lrun_b = 0.f;

    for (int j = 0; j < SS/64; j++) {
        const int buf = j & 3;
        if ((j & 1) == 0) {
            cp_wait<0>();
            __syncthreads();
            if (j + 2 < SS/64) { issueKV(j + 2); issueKV(j + 3); cp_commit(); }
        }

        unsigned ks_base = smem_base + A_KS + buf * 9216;
        unsigned vs_base = smem_base + A_VS + buf * 9216;

        // ---- S' = Q' @ K^T (log2 domain; Q pre-scaled) ----
        float sacc[8][4];
#pragma unroll
        for (int nt = 0; nt < 8; nt++) {
#pragma unroll
            for (int t = 0; t < 4; t++) sacc[nt][t] = 0.f;
        }

#pragma unroll
        for (int kt = 0; kt < 4; kt++) {
#pragma unroll
            for (int ng = 0; ng < 4; ng++) {
                unsigned kr[4];
                ldsm4(kr[0], kr[1], kr[2], kr[3],
                      ks_base + ((ng*16 + k_row)*LDH + kt*16 + k_col) * 2);
                mma16816(sacc[2*ng],   qf[kt], kr);
                mma16816(sacc[2*ng+1], qf[kt], kr + 2);
            }
        }

        // ---- row max (fp32, shfl over quad pair) ----
        float mxa = -INFINITY, mxb = -INFINITY;
#pragma unroll
        for (int nt = 0; nt < 8; nt++) {
            mxa = fmaxf(mxa, fmaxf(sacc[nt][0], sacc[nt][1]));
            mxb = fmaxf(mxb, fmaxf(sacc[nt][2], sacc[nt][3]));
        }
        mxa = fmaxf(mxa, __shfl_xor_sync(0xffffffffu, mxa, 1));
        mxa = fmaxf(mxa, __shfl_xor_sync(0xffffffffu, mxa, 2));
        mxb = fmaxf(mxb, __shfl_xor_sync(0xffffffffu, mxb, 1));
        mxb = fmaxf(mxb, __shfl_xor_sync(0xffffffffu, mxb, 2));

        float mna = fmaxf(mrun_a, mxa), mnb = fmaxf(mrun_b, mxb);

        // ---- p = 2^(s'-m') in fp32, pack straight to fp16 A-fragments ----
        unsigned pa[4][4];
#pragma unroll
        for (int kt = 0; kt < 4; kt++) {
            __half2 h0 = __floats2half2_rn(ex2f(sacc[2*kt][0] - mna),   ex2f(sacc[2*kt][1] - mna));
            __half2 h1 = __floats2half2_rn(ex2f(sacc[2*kt][2] - mnb),   ex2f(sacc[2*kt][3] - mnb));
            __half2 h2 = __floats2half2_rn(ex2f(sacc[2*kt+1][0] - mna), ex2f(sacc[2*kt+1][1] - mna));
            __half2 h3 = __floats2half2_rn(ex2f(sacc[2*kt+1][2] - mnb), ex2f(sacc[2*kt+1][3] - mnb));
            pa[kt][0] = *(unsigned*)&h0;
            pa[kt][1] = *(unsigned*)&h1;
            pa[kt][2] = *(unsigned*)&h2;
            pa[kt][3] = *(unsigned*)&h3;
        }

        // ---- row sums via ones-MMA: every lane's c[0]/c[2] = full row sum ----
        float lsum[4] = {0.f, 0.f, 0.f, 0.f};
#pragma unroll
        for (int kt = 0; kt < 4; kt++)
            mma16816(lsum, pa[kt], ones_b);
        float suma = lsum[0], sumb = lsum[2];

        float alpha_a = ex2f(mrun_a - mna), alpha_b = ex2f(mrun_b - mnb);
        float beta_a = (lrun_a > 0.f) ? (alpha_a / lrun_a) : 0.f;
        float beta_b = (lrun_b > 0.f) ? (alpha_b / lrun_b) : 0.f;
        lrun_a = alpha_a * lrun_a + suma;
        lrun_b = alpha_b * lrun_b + sumb;
        mrun_a = mna; mrun_b = mnb;

        // ---- u = beta*u + P@V ----
#pragma unroll
        for (int nt = 0; nt < 8; nt++) {
            u[nt][0] *= beta_a; u[nt][1] *= beta_a;
            u[nt][2] *= beta_b; u[nt][3] *= beta_b;
        }
#pragma unroll
        for (int kt = 0; kt < 4; kt++) {
#pragma unroll
            for (int dg = 0; dg < 4; dg++) {
                unsigned vr[4];
                ldsm4t(vr[0], vr[1], vr[2], vr[3],
                       vs_base + ((kt*16 + v_row)*LDH + dg*16 + v_col) * 2);
                mma16816(u[2*dg],   pa[kt], vr);
                mma16816(u[2*dg+1], pa[kt], vr + 2);
            }
        }
    }

    float inva = 1.f / lrun_a, invb = 1.f / lrun_b;
    {
        int row_a = qb*128 + r0 + quad;
        __half* base_a = g_O16 + ((size_t)(b * SS + row_a)) * DIM + h * DD;
        __half* base_b = base_a + (size_t)8 * DIM;
#pragma unroll
        for (int nt = 0; nt < 8; nt++) {
            int c = nt*8 + ql*2;
            *(__half2*)(base_a + c) = __floats2half2_rn(u[nt][0] * inva, u[nt][1] * inva);
            *(__half2*)(base_b + c) = __floats2half2_rn(u[nt][2] * invb, u[nt][3] * invb);
        }
    }
}

// ---------------------------------------------------------------------------
extern "C" void kernel_launch(void* const* d_in, const int* in_sizes, int n_in,
                              void* d_out, int out_size)
{
    const float* x  = (const float*)d_in[0];
    const float* Wq = (const float*)d_in[1];
    const float* Wk = (const float*)d_in[2];
    const float* Wv = (const float*)d_in[3];
    const float* Wo = (const float*)d_in[4];

    cudaFuncSetAttribute(qkv16_kernel,   cudaFuncAttributeMaxDynamicSharedMemorySize, PROJ_SMEM);
    cudaFuncSetAttribute(oproj16_kernel, cudaFuncAttributeMaxDynamicSharedMemorySize, PROJ_SMEM);
    cudaFuncSetAttribute(attn_reg_kernel,cudaFuncAttributeMaxDynamicSharedMemorySize, ATT_SMEM);

    __half2* dx;
    cudaGetSymbolAddress((void**)&dx, g_x16);

    const int nx2 = MROWS*DIM/2, nw2 = DIM*DIM/2;
    f2h_kernel<<<(nx2+255)/256, 256>>>((const float2*)x, dx, nx2);
    f2hW_kernel<<<dim3(nw2/256, 1, 4), 256>>>((const float2*)Wq, (const float2*)Wk,
                                              (const float2*)Wv, (const float2*)Wo);

    qkv16_kernel<<<dim3(8, 32, 3), 256, PROJ_SMEM>>>();
    attn_reg_kernel<<<dim3(16, 16, 2), 256, ATT_SMEM>>>();
    oproj16_kernel<<<dim3(8, 32), 256, PROJ_SMEM>>>((float*)d_out);
}

// round 15
// speedup vs baseline: 1.5258x; 1.5258x over previous
#include <cuda_runtime.h>
#include <cuda_fp16.h>
#include <math.h>

#define BB 2
#define SS 2048
#define HH 16
#define DD 64
#define DIM 1024
#define MROWS (BB*SS)

// fp16 staging (device globals; no allocs allowed)
__device__ __align__(16) __half g_x16[MROWS*DIM];
__device__ __align__(16) __half g_Wq16[DIM*DIM];
__device__ __align__(16) __half g_Wk16[DIM*DIM];
__device__ __align__(16) __half g_Wv16[DIM*DIM];
__device__ __align__(16) __half g_Wo16[DIM*DIM];
__device__ __align__(16) __half g_Q16[BB*HH*SS*DD];   // (B,H,S,D), PRE-SCALED by 0.125*log2(e)
__device__ __align__(16) __half g_K16[BB*HH*SS*DD];
__device__ __align__(16) __half g_V16[BB*HH*SS*DD];
__device__ __align__(16) __half g_O16[MROWS*DIM];     // (B,S,H*D)

// ---------------- helpers ----------------
__device__ __forceinline__ void cp16(void* s, const void* g) {
    unsigned saddr = (unsigned)__cvta_generic_to_shared(s);
    asm volatile("cp.async.cg.shared.global [%0], [%1], 16;\n" :: "r"(saddr), "l"(g));
}
__device__ __forceinline__ void cp_commit() { asm volatile("cp.async.commit_group;\n"); }
template<int N> __device__ __forceinline__ void cp_wait() {
    asm volatile("cp.async.wait_group %0;\n" :: "n"(N));
}
__device__ __forceinline__ float ex2f(float x) {           // single EX2 (MUFU)
    float r;
    asm("ex2.approx.f32 %0, %1;" : "=f"(r) : "f"(x));
    return r;
}

__global__ __launch_bounds__(256) void f2h_kernel(const float2* __restrict__ src,
                                                  __half2* __restrict__ dst, int n2) {
    int i = blockIdx.x * blockDim.x + threadIdx.x;
    if (i < n2) { float2 v = src[i]; dst[i] = __floats2half2_rn(v.x, v.y); }
}

__global__ __launch_bounds__(256) void f2hW_kernel(
    const float2* __restrict__ Wq, const float2* __restrict__ Wk,
    const float2* __restrict__ Wv, const float2* __restrict__ Wo)
{
    const float2* src;
    __half2* dst;
    if (blockIdx.z == 0)      { src = Wq; dst = (__half2*)g_Wq16; }
    else if (blockIdx.z == 1) { src = Wk; dst = (__half2*)g_Wk16; }
    else if (blockIdx.z == 2) { src = Wv; dst = (__half2*)g_Wv16; }
    else                      { src = Wo; dst = (__half2*)g_Wo16; }
    int i = blockIdx.x * blockDim.x + threadIdx.x;
    float2 v = src[i];
    dst[i] = __floats2half2_rn(v.x, v.y);
}

// ---------------- mma / ldmatrix PTX ----------------
__device__ __forceinline__ void ldsm4(unsigned& r0, unsigned& r1, unsigned& r2, unsigned& r3, unsigned addr) {
    asm volatile("ldmatrix.sync.aligned.m8n8.x4.shared.b16 {%0,%1,%2,%3}, [%4];\n"
                 : "=r"(r0), "=r"(r1), "=r"(r2), "=r"(r3) : "r"(addr));
}
__device__ __forceinline__ void ldsm4t(unsigned& r0, unsigned& r1, unsigned& r2, unsigned& r3, unsigned addr) {
    asm volatile("ldmatrix.sync.aligned.m8n8.x4.trans.shared.b16 {%0,%1,%2,%3}, [%4];\n"
                 : "=r"(r0), "=r"(r1), "=r"(r2), "=r"(r3) : "r"(addr));
}
__device__ __forceinline__ void mma16816(float* c, const unsigned* a, const unsigned* b) {
    asm volatile("mma.sync.aligned.m16n8k16.row.col.f32.f16.f16.f32 "
                 "{%0,%1,%2,%3}, {%4,%5,%6,%7}, {%8,%9}, {%0,%1,%2,%3};\n"
                 : "+f"(c[0]), "+f"(c[1]), "+f"(c[2]), "+f"(c[3])
                 : "r"(a[0]), "r"(a[1]), "r"(a[2]), "r"(a[3]), "r"(b[0]), "r"(b[1]));
}

// ---------------------------------------------------------------------------
// Projection GEMM (raw mma): 128x128 tile, 256 threads (8 warps, 4x2 grid),
// warp tile 32x64. KC=64, 3-stage cp.async, ONE barrier per chunk,
// register-direct epilogue.
// ---------------------------------------------------------------------------
#define PLA 72
#define PLB 136
#define KC  64
#define NSTG 3
#define A_ST_BYTES (128*PLA*2)     // 18432
#define B_ST_BYTES (KC*PLB*2)      // 17408
#define PROJ_SMEM (NSTG*A_ST_BYTES + NSTG*B_ST_BYTES)   // 107520

struct ProjC { float c[2][8][4]; };

__device__ __forceinline__ void proj_issue(const __half* __restrict__ X,
                                           const __half* __restrict__ W,
                                           char* smem, int m0, int n0, int k0,
                                           int buf, int tid)
{
    __half* As = (__half*)(smem + buf * A_ST_BYTES);
    __half* Bs = (__half*)(smem + NSTG * A_ST_BYTES + buf * B_ST_BYTES);
#pragma unroll
    for (int i = tid; i < 1024; i += 256) {
        int r = i >> 3, c = (i & 7) << 3;
        cp16(As + r*PLA + c, X + (size_t)(m0 + r)*DIM + k0 + c);
    }
#pragma unroll
    for (int i = tid; i < 1024; i += 256) {
        int r = i >> 4, c = (i & 15) << 3;
        cp16(Bs + r*PLB + c, W + (size_t)(k0 + r)*DIM + n0 + c);
    }
}

__device__ __forceinline__ void proj_mainloop_raw(
    const __half* __restrict__ X, const __half* __restrict__ W,
    int m0, int n0, char* smem, int tid, ProjC& P)
{
    const int wid = tid >> 5, lane = tid & 31;
    const int wm = wid >> 1, wn = wid & 1;
    const int l8 = lane & 7, g = lane >> 3;
    const int a_row = (g & 1) * 8 + l8, a_col = (g >> 1) * 8;
    const int b_row = (g & 1) * 8 + l8, b_col = (g >> 1) * 8;

#pragma unroll
    for (int i = 0; i < 2; i++)
#pragma unroll
        for (int j = 0; j < 8; j++)
#pragma unroll
            for (int t = 0; t < 4; t++) P.c[i][j][t] = 0.f;

    const unsigned smem_u = (unsigned)__cvta_generic_to_shared(smem);

    proj_issue(X, W, smem, m0, n0, 0, 0, tid); cp_commit();
    proj_issue(X, W, smem, m0, n0, KC, 1, tid); cp_commit();

    const int NIT = DIM / KC;
    for (int it = 0; it < NIT; it++) {
        int buf = it % NSTG;
        if (it + 1 < NIT) cp_wait<1>(); else cp_wait<0>();
        __syncthreads();
        if (it + 2 < NIT) { proj_issue(X, W, smem, m0, n0, (it + 2) * KC, (it + 2) % NSTG, tid); cp_commit(); }

        unsigned as_base = smem_u + buf * A_ST_BYTES;
        unsigned bs_base = smem_u + NSTG * A_ST_BYTES + buf * B_ST_BYTES;

#pragma unroll
        for (int kk = 0; kk < KC/16; kk++) {
            unsigned af[2][4];
#pragma unroll
            for (int i = 0; i < 2; i++)
                ldsm4(af[i][0], af[i][1], af[i][2], af[i][3],
                      as_base + (unsigned)(((wm*32 + i*16 + a_row)*PLA + kk*16 + a_col) * 2));
#pragma unroll
            for (int ng = 0; ng < 4; ng++) {
                unsigned br[4];
                ldsm4t(br[0], br[1], br[2], br[3],
                       bs_base + (unsigned)(((kk*16 + b_row)*PLB + wn*64 + ng*16 + b_col) * 2));
                mma16816(P.c[0][2*ng],   af[0], br);
                mma16816(P.c[0][2*ng+1], af[0], br + 2);
                mma16816(P.c[1][2*ng],   af[1], br);
                mma16816(P.c[1][2*ng+1], af[1], br + 2);
            }
        }
    }
}

__global__ __launch_bounds__(256,2) void qkv16_kernel()
{
    extern __shared__ __align__(16) char smem[];

    const __half* W; __half* out;
    if (blockIdx.z == 0)      { W = g_Wq16; out = g_Q16; }
    else if (blockIdx.z == 1) { W = g_Wk16; out = g_K16; }
    else                      { W = g_Wv16; out = g_V16; }
    // Q gets 0.125 * log2(e): softmax runs in log2 domain (p = 2^(s'-m')).
    const float fscale = (blockIdx.z == 0) ? 0.18033688011118324f : 1.0f;

    const int tid = threadIdx.x, wid = tid >> 5, lane = tid & 31;
    const int wm = wid >> 1, wn = wid & 1;
    const int quad = lane >> 2, ql = lane & 3;
    const int m0 = blockIdx.y * 128, n0 = blockIdx.x * 128;

    ProjC P;
    proj_mainloop_raw(g_x16, W, m0, n0, smem, tid, P);

    const int bb = m0 >> 11, s0 = m0 & 2047;
    const int h = (n0 >> 6) + wn;
    __half* hb = out + (size_t)((bb << 4) + h) * SS * DD;
#pragma unroll
    for (int i = 0; i < 2; i++) {
        int ra = s0 + wm*32 + i*16 + quad;
        __half* pa_ = hb + (size_t)ra * DD;
        __half* pb_ = pa_ + 8 * DD;
#pragma unroll
        for (int j = 0; j < 8; j++) {
            int cc = j*8 + ql*2;
            *(__half2*)(pa_ + cc) = __floats2half2_rn(P.c[i][j][0]*fscale, P.c[i][j][1]*fscale);
            *(__half2*)(pb_ + cc) = __floats2half2_rn(P.c[i][j][2]*fscale, P.c[i][j][3]*fscale);
        }
    }
}

__global__ __launch_bounds__(256,2) void oproj16_kernel(float* __restrict__ C)
{
    extern __shared__ __align__(16) char smem[];
    const int tid = threadIdx.x, wid = tid >> 5, lane = tid & 31;
    const int wm = wid >> 1, wn = wid & 1;
    const int quad = lane >> 2, ql = lane & 3;
    const int m0 = blockIdx.y * 128, n0 = blockIdx.x * 128;

    ProjC P;
    proj_mainloop_raw(g_O16, g_Wo16, m0, n0, smem, tid, P);

#pragma unroll
    for (int i = 0; i < 2; i++) {
        float* pa_ = C + (size_t)(m0 + wm*32 + i*16 + quad) * DIM + n0 + wn*64;
        float* pb_ = pa_ + 8 * DIM;
#pragma unroll
        for (int j = 0; j < 8; j++) {
            int cc = j*8 + ql*2;
            *(float2*)(pa_ + cc) = make_float2(P.c[i][j][0], P.c[i][j][1]);
            *(float2*)(pb_ + cc) = make_float2(P.c[i][j][2], P.c[i][j][3]);
        }
    }
}

// ---------------------------------------------------------------------------
// Attention: register-resident FMHA (R11 structure), BQ=128, 8 warps,
// 4 KV buffers, 2 blocks per barrier. log2-domain softmax:
//   Q pre-scaled by 0.125*log2e, p = ex2(s'-m'), alpha = ex2(m'old-m'new).
// Sum accumulated inline with exp loop (ILP), shfl reductions kept.
// Division folded: u_j = (alpha_j/l_{j-1}) u_{j-1} + P_j V_j;  o = u_N / l_N.
// ---------------------------------------------------------------------------
#define LDH 72
#define A_QS   0
#define A_KS   18432
#define A_VS   (18432 + 4*9216)
#define ATT_SMEM (18432 + 8*9216)          // 92160

__global__ __launch_bounds__(256,2) void attn_reg_kernel()
{
    extern __shared__ __align__(16) char smem[];
    __half* Qs = (__half*)(smem + A_QS);

    const int tid = threadIdx.x, wid = tid >> 5, lane = tid & 31;
    const int qb = blockIdx.x, h = blockIdx.y, b = blockIdx.z;
    const int r0 = wid * 16;
    const int l8 = lane & 7, g = lane >> 3;
    const int quad = lane >> 2, ql = lane & 3;

    const __half* Qg  = g_Q16 + ((size_t)((b << 4) + h) * SS + qb * 128) * DD;
    const __half* Kg0 = g_K16 + (size_t)((b << 4) + h) * SS * DD;
    const __half* Vg0 = g_V16 + (size_t)((b << 4) + h) * SS * DD;

    auto issueKV = [&](int j) {
        int buf = j & 3;
        __half* Ks = (__half*)(smem + A_KS + buf * 9216);
        __half* Vs = (__half*)(smem + A_VS + buf * 9216);
        const __half* Kg = Kg0 + (size_t)j * (64*DD);
        const __half* Vg = Vg0 + (size_t)j * (64*DD);
#pragma unroll
        for (int i = tid; i < 512; i += 256) {
            int r = i >> 3, c = (i & 7) << 3;
            cp16(Ks + r*LDH + c, Kg + r*DD + c);
            cp16(Vs + r*LDH + c, Vg + r*DD + c);
        }
    };

    issueKV(0); issueKV(1); cp_commit();

#pragma unroll
    for (int i = tid; i < 1024; i += 256) {
        int r = i >> 3, c = (i & 7) << 3;
        *(uint4*)(Qs + r*LDH + c) = *(const uint4*)(Qg + r*DD + c);
    }
    __syncthreads();

    unsigned qs_base = (unsigned)__cvta_generic_to_shared(Qs);
    unsigned qf[4][4];
    {
        int qrow = r0 + (g & 1) * 8 + l8;
        int qcol = (g >> 1) * 8;
#pragma unroll
        for (int kt = 0; kt < 4; kt++) {
            ldsm4(qf[kt][0], qf[kt][1], qf[kt][2], qf[kt][3],
                  qs_base + (qrow*LDH + kt*16 + qcol) * 2);
        }
    }

    const int k_row = (g >> 1) * 8 + l8, k_col = (g & 1) * 8;
    const int v_row = (g & 1) * 8 + l8,  v_col = (g >> 1) * 8;
    const unsigned smem_base = (unsigned)__cvta_generic_to_shared(smem);

    float u[8][4];
#pragma unroll
    for (int nt = 0; nt < 8; nt++) {
#pragma unroll
        for (int t = 0; t < 4; t++) u[nt][t] = 0.f;
    }

    float mrun_a = -INFINITY, mrun_b = -INFINITY, lrun_a = 0.f, lrun_b = 0.f;

    auto process_block = [&](int j) {
        int buf = j & 3;
        unsigned ks_base = smem_base + A_KS + buf * 9216;
        unsigned vs_base = smem_base + A_VS + buf * 9216;

        // ---- S' = Q' @ K^T (log2 domain) ----
        float sacc[8][4];
#pragma unroll
        for (int nt = 0; nt < 8; nt++) {
#pragma unroll
            for (int t = 0; t < 4; t++) sacc[nt][t] = 0.f;
        }

#pragma unroll
        for (int kt = 0; kt < 4; kt++) {
#pragma unroll
            for (int ng = 0; ng < 4; ng++) {
                unsigned kr[4];
                ldsm4(kr[0], kr[1], kr[2], kr[3],
                      ks_base + ((ng*16 + k_row)*LDH + kt*16 + k_col) * 2);
                mma16816(sacc[2*ng],   qf[kt], kr);
                mma16816(sacc[2*ng+1], qf[kt], kr + 2);
            }
        }

        // ---- online softmax (rows quad, quad+8); p = 2^(s'-m') ----
        float mxa = -INFINITY, mxb = -INFINITY;
#pragma unroll
        for (int nt = 0; nt < 8; nt++) {
            mxa = fmaxf(mxa, fmaxf(sacc[nt][0], sacc[nt][1]));
            mxb = fmaxf(mxb, fmaxf(sacc[nt][2], sacc[nt][3]));
        }
        mxa = fmaxf(mxa, __shfl_xor_sync(0xffffffffu, mxa, 1));
        mxa = fmaxf(mxa, __shfl_xor_sync(0xffffffffu, mxa, 2));
        mxb = fmaxf(mxb, __shfl_xor_sync(0xffffffffu, mxb, 1));
        mxb = fmaxf(mxb, __shfl_xor_sync(0xffffffffu, mxb, 2));

        float mna = fmaxf(mrun_a, mxa), mnb = fmaxf(mrun_b, mxb);
        float suma = 0.f, sumb = 0.f;
#pragma unroll
        for (int nt = 0; nt < 8; nt++) {
            sacc[nt][0] = ex2f(sacc[nt][0] - mna);
            sacc[nt][1] = ex2f(sacc[nt][1] - mna);
            sacc[nt][2] = ex2f(sacc[nt][2] - mnb);
            sacc[nt][3] = ex2f(sacc[nt][3] - mnb);
            suma += sacc[nt][0] + sacc[nt][1];
            sumb += sacc[nt][2] + sacc[nt][3];
        }
        suma += __shfl_xor_sync(0xffffffffu, suma, 1);
        suma += __shfl_xor_sync(0xffffffffu, suma, 2);
        sumb += __shfl_xor_sync(0xffffffffu, sumb, 1);
        sumb += __shfl_xor_sync(0xffffffffu, sumb, 2);

        float alpha_a = ex2f(mrun_a - mna), alpha_b = ex2f(mrun_b - mnb);
        float beta_a = (lrun_a > 0.f) ? (alpha_a / lrun_a) : 0.f;
        float beta_b = (lrun_b > 0.f) ? (alpha_b / lrun_b) : 0.f;
        lrun_a = alpha_a * lrun_a + suma;
        lrun_b = alpha_b * lrun_b + sumb;
        mrun_a = mna; mrun_b = mnb;

        // ---- pack P (fp16) into A-fragments ----
        unsigned pa[4][4];
#pragma unroll
        for (int kt = 0; kt < 4; kt++) {
            __half2 h0 = __floats2half2_rn(sacc[2*kt][0],   sacc[2*kt][1]);
            __half2 h1 = __floats2half2_rn(sacc[2*kt][2],   sacc[2*kt][3]);
            __half2 h2 = __floats2half2_rn(sacc[2*kt+1][0], sacc[2*kt+1][1]);
            __half2 h3 = __floats2half2_rn(sacc[2*kt+1][2], sacc[2*kt+1][3]);
            pa[kt][0] = *(unsigned*)&h0;
            pa[kt][1] = *(unsigned*)&h1;
            pa[kt][2] = *(unsigned*)&h2;
            pa[kt][3] = *(unsigned*)&h3;
        }

        // ---- u = beta*u + P@V ----
#pragma unroll
        for (int nt = 0; nt < 8; nt++) {
            u[nt][0] *= beta_a; u[nt][1] *= beta_a;
            u[nt][2] *= beta_b; u[nt][3] *= beta_b;
        }
#pragma unroll
        for (int kt = 0; kt < 4; kt++) {
#pragma unroll
            for (int dg = 0; dg < 4; dg++) {
                unsigned vr[4];
                ldsm4t(vr[0], vr[1], vr[2], vr[3],
                       vs_base + ((kt*16 + v_row)*LDH + dg*16 + v_col) * 2);
                mma16816(u[2*dg],   pa[kt], vr);
                mma16816(u[2*dg+1], pa[kt], vr + 2);
            }
        }
    };

    for (int gi = 0; gi < SS/128; gi++) {
        cp_wait<0>();
        __syncthreads();
        if (gi + 1 < SS/128) { issueKV(2*gi + 2); issueKV(2*gi + 3); cp_commit(); }
        process_block(2*gi);
        process_block(2*gi + 1);
    }

    float inva = 1.f / lrun_a, invb = 1.f / lrun_b;
    {
        int row_a = qb*128 + r0 + quad;
        __half* base_a = g_O16 + ((size_t)(b * SS + row_a)) * DIM + h * DD;
        __half* base_b = base_a + (size_t)8 * DIM;
#pragma unroll
        for (int nt = 0; nt < 8; nt++) {
            int c = nt*8 + ql*2;
            *(__half2*)(base_a + c) = __floats2half2_rn(u[nt][0] * inva, u[nt][1] * inva);
            *(__half2*)(base_b + c) = __floats2half2_rn(u[nt][2] * invb, u[nt][3] * invb);
        }
    }
}

// ---------------------------------------------------------------------------
extern "C" void kernel_launch(void* const* d_in, const int* in_sizes, int n_in,
                              void* d_out, int out_size)
{
    const float* x  = (const float*)d_in[0];
    const float* Wq = (const float*)d_in[1];
    const float* Wk = (const float*)d_in[2];
    const float* Wv = (const float*)d_in[3];
    const float* Wo = (const float*)d_in[4];

    cudaFuncSetAttribute(qkv16_kernel,   cudaFuncAttributeMaxDynamicSharedMemorySize, PROJ_SMEM);
    cudaFuncSetAttribute(oproj16_kernel, cudaFuncAttributeMaxDynamicSharedMemorySize, PROJ_SMEM);
    cudaFuncSetAttribute(attn_reg_kernel,cudaFuncAttributeMaxDynamicSharedMemorySize, ATT_SMEM);

    __half2* dx;
    cudaGetSymbolAddress((void**)&dx, g_x16);

    const int nx2 = MROWS*DIM/2, nw2 = DIM*DIM/2;
    f2h_kernel<<<(nx2+255)/256, 256>>>((const float2*)x, dx, nx2);
    f2hW_kernel<<<dim3(nw2/256, 1, 4), 256>>>((const float2*)Wq, (const float2*)Wk,
                                              (const float2*)Wv, (const float2*)Wo);

    qkv16_kernel<<<dim3(8, 32, 3), 256, PROJ_SMEM>>>();
    attn_reg_kernel<<<dim3(16, 16, 2), 256, ATT_SMEM>>>();
    oproj16_kernel<<<dim3(8, 32), 256, PROJ_SMEM>>>((float*)d_out);
}

// round 16
// speedup vs baseline: 1.5330x; 1.0047x over previous
#include <cuda_runtime.h>
#include <cuda_fp16.h>
#include <math.h>

#define BB 2
#define SS 2048
#define HH 16
#define DD 64
#define DIM 1024
#define MROWS (BB*SS)

// fp16 staging (device globals; no allocs allowed)
__device__ __align__(16) __half g_x16[MROWS*DIM];
__device__ __align__(16) __half g_Wq16[DIM*DIM];
__device__ __align__(16) __half g_Wk16[DIM*DIM];
__device__ __align__(16) __half g_Wv16[DIM*DIM];
__device__ __align__(16) __half g_Wo16[DIM*DIM];
__device__ __align__(16) __half g_Q16[BB*HH*SS*DD];   // (B,H,S,D), PRE-SCALED by 0.125*log2(e)
__device__ __align__(16) __half g_K16[BB*HH*SS*DD];
__device__ __align__(16) __half g_V16[BB*HH*SS*DD];
__device__ __align__(16) __half g_O16[MROWS*DIM];     // (B,S,H*D)

// ---------------- helpers ----------------
__device__ __forceinline__ void cp16(void* s, const void* g) {
    unsigned saddr = (unsigned)__cvta_generic_to_shared(s);
    asm volatile("cp.async.cg.shared.global [%0], [%1], 16;\n" :: "r"(saddr), "l"(g));
}
__device__ __forceinline__ void cp_commit() { asm volatile("cp.async.commit_group;\n"); }
template<int N> __device__ __forceinline__ void cp_wait() {
    asm volatile("cp.async.wait_group %0;\n" :: "n"(N));
}
__device__ __forceinline__ float ex2f(float x) {           // single EX2 (MUFU)
    float r;
    asm("ex2.approx.f32 %0, %1;" : "=f"(r) : "f"(x));
    return r;
}

// Single fused conversion kernel: x (2^21 half2) then Wq,Wk,Wv,Wo (2^19 half2 each).
#define NX2 (MROWS*DIM/2)         // 2097152 = 1<<21
#define NW2 (DIM*DIM/2)           // 524288  = 1<<19
#define NCVT (NX2 + 4*NW2)        // 4194304

__global__ __launch_bounds__(256) void cvt_all_kernel(
    const float2* __restrict__ x,  const float2* __restrict__ Wq,
    const float2* __restrict__ Wk, const float2* __restrict__ Wv,
    const float2* __restrict__ Wo)
{
    int i = blockIdx.x * blockDim.x + threadIdx.x;
    const float2* src;
    __half2* dst;
    int j;
    if (i < NX2) {
        src = x; dst = (__half2*)g_x16; j = i;
    } else {
        int k = i - NX2;
        int w = k >> 19;
        j = k & (NW2 - 1);
        if (w == 0)      { src = Wq; dst = (__half2*)g_Wq16; }
        else if (w == 1) { src = Wk; dst = (__half2*)g_Wk16; }
        else if (w == 2) { src = Wv; dst = (__half2*)g_Wv16; }
        else             { src = Wo; dst = (__half2*)g_Wo16; }
    }
    float2 v = src[j];
    dst[j] = __floats2half2_rn(v.x, v.y);
}

// ---------------- mma / ldmatrix PTX ----------------
__device__ __forceinline__ void ldsm4(unsigned& r0, unsigned& r1, unsigned& r2, unsigned& r3, unsigned addr) {
    asm volatile("ldmatrix.sync.aligned.m8n8.x4.shared.b16 {%0,%1,%2,%3}, [%4];\n"
                 : "=r"(r0), "=r"(r1), "=r"(r2), "=r"(r3) : "r"(addr));
}
__device__ __forceinline__ void ldsm4t(unsigned& r0, unsigned& r1, unsigned& r2, unsigned& r3, unsigned addr) {
    asm volatile("ldmatrix.sync.aligned.m8n8.x4.trans.shared.b16 {%0,%1,%2,%3}, [%4];\n"
                 : "=r"(r0), "=r"(r1), "=r"(r2), "=r"(r3) : "r"(addr));
}
__device__ __forceinline__ void mma16816(float* c, const unsigned* a, const unsigned* b) {
    asm volatile("mma.sync.aligned.m16n8k16.row.col.f32.f16.f16.f32 "
                 "{%0,%1,%2,%3}, {%4,%5,%6,%7}, {%8,%9}, {%0,%1,%2,%3};\n"
                 : "+f"(c[0]), "+f"(c[1]), "+f"(c[2]), "+f"(c[3])
                 : "r"(a[0]), "r"(a[1]), "r"(a[2]), "r"(a[3]), "r"(b[0]), "r"(b[1]));
}

// ---------------------------------------------------------------------------
// Projection GEMM (raw mma): 128x128 tile, 256 threads (8 warps, 4x2 grid),
// warp tile 32x64. KC=64, 3-stage cp.async, ONE barrier per chunk,
// register-direct epilogue.
// ---------------------------------------------------------------------------
#define PLA 72
#define PLB 136
#define KC  64
#define NSTG 3
#define A_ST_BYTES (128*PLA*2)     // 18432
#define B_ST_BYTES (KC*PLB*2)      // 17408
#define PROJ_SMEM (NSTG*A_ST_BYTES + NSTG*B_ST_BYTES)   // 107520

struct ProjC { float c[2][8][4]; };

__device__ __forceinline__ void proj_issue(const __half* __restrict__ X,
                                           const __half* __restrict__ W,
                                           char* smem, int m0, int n0, int k0,
                                           int buf, int tid)
{
    __half* As = (__half*)(smem + buf * A_ST_BYTES);
    __half* Bs = (__half*)(smem + NSTG * A_ST_BYTES + buf * B_ST_BYTES);
#pragma unroll
    for (int i = tid; i < 1024; i += 256) {
        int r = i >> 3, c = (i & 7) << 3;
        cp16(As + r*PLA + c, X + (size_t)(m0 + r)*DIM + k0 + c);
    }
#pragma unroll
    for (int i = tid; i < 1024; i += 256) {
        int r = i >> 4, c = (i & 15) << 3;
        cp16(Bs + r*PLB + c, W + (size_t)(k0 + r)*DIM + n0 + c);
    }
}

__device__ __forceinline__ void proj_mainloop_raw(
    const __half* __restrict__ X, const __half* __restrict__ W,
    int m0, int n0, char* smem, int tid, ProjC& P)
{
    const int wid = tid >> 5, lane = tid & 31;
    const int wm = wid >> 1, wn = wid & 1;
    const int l8 = lane & 7, g = lane >> 3;
    const int a_row = (g & 1) * 8 + l8, a_col = (g >> 1) * 8;
    const int b_row = (g & 1) * 8 + l8, b_col = (g >> 1) * 8;

#pragma unroll
    for (int i = 0; i < 2; i++)
#pragma unroll
        for (int j = 0; j < 8; j++)
#pragma unroll
            for (int t = 0; t < 4; t++) P.c[i][j][t] = 0.f;

    const unsigned smem_u = (unsigned)__cvta_generic_to_shared(smem);

    proj_issue(X, W, smem, m0, n0, 0, 0, tid); cp_commit();
    proj_issue(X, W, smem, m0, n0, KC, 1, tid); cp_commit();

    const int NIT = DIM / KC;
    for (int it = 0; it < NIT; it++) {
        int buf = it % NSTG;
        if (it + 1 < NIT) cp_wait<1>(); else cp_wait<0>();
        __syncthreads();
        if (it + 2 < NIT) { proj_issue(X, W, smem, m0, n0, (it + 2) * KC, (it + 2) % NSTG, tid); cp_commit(); }

        unsigned as_base = smem_u + buf * A_ST_BYTES;
        unsigned bs_base = smem_u + NSTG * A_ST_BYTES + buf * B_ST_BYTES;

#pragma unroll
        for (int kk = 0; kk < KC/16; kk++) {
            unsigned af[2][4];
#pragma unroll
            for (int i = 0; i < 2; i++)
                ldsm4(af[i][0], af[i][1], af[i][2], af[i][3],
                      as_base + (unsigned)(((wm*32 + i*16 + a_row)*PLA + kk*16 + a_col) * 2));
#pragma unroll
            for (int ng = 0; ng < 4; ng++) {
                unsigned br[4];
                ldsm4t(br[0], br[1], br[2], br[3],
                       bs_base + (unsigned)(((kk*16 + b_row)*PLB + wn*64 + ng*16 + b_col) * 2));
                mma16816(P.c[0][2*ng],   af[0], br);
                mma16816(P.c[0][2*ng+1], af[0], br + 2);
                mma16816(P.c[1][2*ng],   af[1], br);
                mma16816(P.c[1][2*ng+1], af[1], br + 2);
            }
        }
    }
}

__global__ __launch_bounds__(256,2) void qkv16_kernel()
{
    extern __shared__ __align__(16) char smem[];

    const __half* W; __half* out;
    if (blockIdx.z == 0)      { W = g_Wq16; out = g_Q16; }
    else if (blockIdx.z == 1) { W = g_Wk16; out = g_K16; }
    else                      { W = g_Wv16; out = g_V16; }
    // Q gets 0.125 * log2(e): softmax runs in log2 domain (p = 2^(s'-m')).
    const float fscale = (blockIdx.z == 0) ? 0.18033688011118324f : 1.0f;

    const int tid = threadIdx.x, wid = tid >> 5, lane = tid & 31;
    const int wm = wid >> 1, wn = wid & 1;
    const int quad = lane >> 2, ql = lane & 3;
    const int m0 = blockIdx.y * 128, n0 = blockIdx.x * 128;

    ProjC P;
    proj_mainloop_raw(g_x16, W, m0, n0, smem, tid, P);

    const int bb = m0 >> 11, s0 = m0 & 2047;
    const int h = (n0 >> 6) + wn;
    __half* hb = out + (size_t)((bb << 4) + h) * SS * DD;
#pragma unroll
    for (int i = 0; i < 2; i++) {
        int ra = s0 + wm*32 + i*16 + quad;
        __half* pa_ = hb + (size_t)ra * DD;
        __half* pb_ = pa_ + 8 * DD;
#pragma unroll
        for (int j = 0; j < 8; j++) {
            int cc = j*8 + ql*2;
            *(__half2*)(pa_ + cc) = __floats2half2_rn(P.c[i][j][0]*fscale, P.c[i][j][1]*fscale);
            *(__half2*)(pb_ + cc) = __floats2half2_rn(P.c[i][j][2]*fscale, P.c[i][j][3]*fscale);
        }
    }
}

__global__ __launch_bounds__(256,2) void oproj16_kernel(float* __restrict__ C)
{
    extern __shared__ __align__(16) char smem[];
    const int tid = threadIdx.x, wid = tid >> 5, lane = tid & 31;
    const int wm = wid >> 1, wn = wid & 1;
    const int quad = lane >> 2, ql = lane & 3;
    const int m0 = blockIdx.y * 128, n0 = blockIdx.x * 128;

    ProjC P;
    proj_mainloop_raw(g_O16, g_Wo16, m0, n0, smem, tid, P);

#pragma unroll
    for (int i = 0; i < 2; i++) {
        float* pa_ = C + (size_t)(m0 + wm*32 + i*16 + quad) * DIM + n0 + wn*64;
        float* pb_ = pa_ + 8 * DIM;
#pragma unroll
        for (int j = 0; j < 8; j++) {
            int cc = j*8 + ql*2;
            *(float2*)(pa_ + cc) = make_float2(P.c[i][j][0], P.c[i][j][1]);
            *(float2*)(pb_ + cc) = make_float2(P.c[i][j][2], P.c[i][j][3]);
        }
    }
}

// ---------------------------------------------------------------------------
// Attention: register-resident FMHA, BQ=128, 8 warps, 4 KV buffers,
// 2 blocks per barrier. log2-domain softmax (Q pre-scaled by 0.125*log2e):
//   p = ex2(s'-m'), alpha = ex2(m'old-m'new). Sum inline with exp loop.
// Division folded: u_j = (alpha_j/l_{j-1}) u_{j-1} + P_j V_j;  o = u_N / l_N.
// ---------------------------------------------------------------------------
#define LDH 72
#define A_QS   0
#define A_KS   18432
#define A_VS   (18432 + 4*9216)
#define ATT_SMEM (18432 + 8*9216)          // 92160

__global__ __launch_bounds__(256,2) void attn_reg_kernel()
{
    extern __shared__ __align__(16) char smem[];
    __half* Qs = (__half*)(smem + A_QS);

    const int tid = threadIdx.x, wid = tid >> 5, lane = tid & 31;
    const int qb = blockIdx.x, h = blockIdx.y, b = blockIdx.z;
    const int r0 = wid * 16;
    const int l8 = lane & 7, g = lane >> 3;
    const int quad = lane >> 2, ql = lane & 3;

    const __half* Qg  = g_Q16 + ((size_t)((b << 4) + h) * SS + qb * 128) * DD;
    const __half* Kg0 = g_K16 + (size_t)((b << 4) + h) * SS * DD;
    const __half* Vg0 = g_V16 + (size_t)((b << 4) + h) * SS * DD;

    auto issueKV = [&](int j) {
        int buf = j & 3;
        __half* Ks = (__half*)(smem + A_KS + buf * 9216);
        __half* Vs = (__half*)(smem + A_VS + buf * 9216);
        const __half* Kg = Kg0 + (size_t)j * (64*DD);
        const __half* Vg = Vg0 + (size_t)j * (64*DD);
#pragma unroll
        for (int i = tid; i < 512; i += 256) {
            int r = i >> 3, c = (i & 7) << 3;
            cp16(Ks + r*LDH + c, Kg + r*DD + c);
            cp16(Vs + r*LDH + c, Vg + r*DD + c);
        }
    };

    issueKV(0); issueKV(1); cp_commit();

#pragma unroll
    for (int i = tid; i < 1024; i += 256) {
        int r = i >> 3, c = (i & 7) << 3;
        *(uint4*)(Qs + r*LDH + c) = *(const uint4*)(Qg + r*DD + c);
    }
    __syncthreads();

    unsigned qs_base = (unsigned)__cvta_generic_to_shared(Qs);
    unsigned qf[4][4];
    {
        int qrow = r0 + (g & 1) * 8 + l8;
        int qcol = (g >> 1) * 8;
#pragma unroll
        for (int kt = 0; kt < 4; kt++) {
            ldsm4(qf[kt][0], qf[kt][1], qf[kt][2], qf[kt][3],
                  qs_base + (qrow*LDH + kt*16 + qcol) * 2);
        }
    }

    const int k_row = (g >> 1) * 8 + l8, k_col = (g & 1) * 8;
    const int v_row = (g & 1) * 8 + l8,  v_col = (g >> 1) * 8;
    const unsigned smem_base = (unsigned)__cvta_generic_to_shared(smem);

    float u[8][4];
#pragma unroll
    for (int nt = 0; nt < 8; nt++) {
#pragma unroll
        for (int t = 0; t < 4; t++) u[nt][t] = 0.f;
    }

    float mrun_a = -INFINITY, mrun_b = -INFINITY, lrun_a = 0.f, lrun_b = 0.f;

    auto process_block = [&](int j) {
        int buf = j & 3;
        unsigned ks_base = smem_base + A_KS + buf * 9216;
        unsigned vs_base = smem_base + A_VS + buf * 9216;

        // ---- S' = Q' @ K^T (log2 domain) ----
        float sacc[8][4];
#pragma unroll
        for (int nt = 0; nt < 8; nt++) {
#pragma unroll
            for (int t = 0; t < 4; t++) sacc[nt][t] = 0.f;
        }

#pragma unroll
        for (int kt = 0; kt < 4; kt++) {
#pragma unroll
            for (int ng = 0; ng < 4; ng++) {
                unsigned kr[4];
                ldsm4(kr[0], kr[1], kr[2], kr[3],
                      ks_base + ((ng*16 + k_row)*LDH + kt*16 + k_col) * 2);
                mma16816(sacc[2*ng],   qf[kt], kr);
                mma16816(sacc[2*ng+1], qf[kt], kr + 2);
            }
        }

        // ---- online softmax (rows quad, quad+8); p = 2^(s'-m') ----
        float mxa = -INFINITY, mxb = -INFINITY;
#pragma unroll
        for (int nt = 0; nt < 8; nt++) {
            mxa = fmaxf(mxa, fmaxf(sacc[nt][0], sacc[nt][1]));
            mxb = fmaxf(mxb, fmaxf(sacc[nt][2], sacc[nt][3]));
        }
        mxa = fmaxf(mxa, __shfl_xor_sync(0xffffffffu, mxa, 1));
        mxa = fmaxf(mxa, __shfl_xor_sync(0xffffffffu, mxa, 2));
        mxb = fmaxf(mxb, __shfl_xor_sync(0xffffffffu, mxb, 1));
        mxb = fmaxf(mxb, __shfl_xor_sync(0xffffffffu, mxb, 2));

        float mna = fmaxf(mrun_a, mxa), mnb = fmaxf(mrun_b, mxb);
        float suma = 0.f, sumb = 0.f;
#pragma unroll
        for (int nt = 0; nt < 8; nt++) {
            sacc[nt][0] = ex2f(sacc[nt][0] - mna);
            sacc[nt][1] = ex2f(sacc[nt][1] - mna);
            sacc[nt][2] = ex2f(sacc[nt][2] - mnb);
            sacc[nt][3] = ex2f(sacc[nt][3] - mnb);
            suma += sacc[nt][0] + sacc[nt][1];
            sumb += sacc[nt][2] + sacc[nt][3];
        }
        suma += __shfl_xor_sync(0xffffffffu, suma, 1);
        suma += __shfl_xor_sync(0xffffffffu, suma, 2);
        sumb += __shfl_xor_sync(0xffffffffu, sumb, 1);
        sumb += __shfl_xor_sync(0xffffffffu, sumb, 2);

        float alpha_a = ex2f(mrun_a - mna), alpha_b = ex2f(mrun_b - mnb);
        float beta_a = (lrun_a > 0.f) ? (alpha_a / lrun_a) : 0.f;
        float beta_b = (lrun_b > 0.f) ? (alpha_b / lrun_b) : 0.f;
        lrun_a = alpha_a * lrun_a + suma;
        lrun_b = alpha_b * lrun_b + sumb;
        mrun_a = mna; mrun_b = mnb;

        // ---- pack P (fp16) into A-fragments ----
        unsigned pa[4][4];
#pragma unroll
        for (int kt = 0; kt < 4; kt++) {
            __half2 h0 = __floats2half2_rn(sacc[2*kt][0],   sacc[2*kt][1]);
            __half2 h1 = __floats2half2_rn(sacc[2*kt][2],   sacc[2*kt][3]);
            __half2 h2 = __floats2half2_rn(sacc[2*kt+1][0], sacc[2*kt+1][1]);
            __half2 h3 = __floats2half2_rn(sacc[2*kt+1][2], sacc[2*kt+1][3]);
            pa[kt][0] = *(unsigned*)&h0;
            pa[kt][1] = *(unsigned*)&h1;
            pa[kt][2] = *(unsigned*)&h2;
            pa[kt][3] = *(unsigned*)&h3;
        }

        // ---- u = beta*u + P@V ----
#pragma unroll
        for (int nt = 0; nt < 8; nt++) {
            u[nt][0] *= beta_a; u[nt][1] *= beta_a;
            u[nt][2] *= beta_b; u[nt][3] *= beta_b;
        }
#pragma unroll
        for (int kt = 0; kt < 4; kt++) {
#pragma unroll
            for (int dg = 0; dg < 4; dg++) {
                unsigned vr[4];
                ldsm4t(vr[0], vr[1], vr[2], vr[3],
                       vs_base + ((kt*16 + v_row)*LDH + dg*16 + v_col) * 2);
                mma16816(u[2*dg],   pa[kt], vr);
                mma16816(u[2*dg+1], pa[kt], vr + 2);
            }
        }
    };

    for (int gi = 0; gi < SS/128; gi++) {
        cp_wait<0>();
        __syncthreads();
        if (gi + 1 < SS/128) { issueKV(2*gi + 2); issueKV(2*gi + 3); cp_commit(); }
        process_block(2*gi);
        process_block(2*gi + 1);
    }

    float inva = 1.f / lrun_a, invb = 1.f / lrun_b;
    {
        int row_a = qb*128 + r0 + quad;
        __half* base_a = g_O16 + ((size_t)(b * SS + row_a)) * DIM + h * DD;
        __half* base_b = base_a + (size_t)8 * DIM;
#pragma unroll
        for (int nt = 0; nt < 8; nt++) {
            int c = nt*8 + ql*2;
            *(__half2*)(base_a + c) = __floats2half2_rn(u[nt][0] * inva, u[nt][1] * inva);
            *(__half2*)(base_b + c) = __floats2half2_rn(u[nt][2] * invb, u[nt][3] * invb);
        }
    }
}

// ---------------------------------------------------------------------------
extern "C" void kernel_launch(void* const* d_in, const int* in_sizes, int n_in,
                              void* d_out, int out_size)
{
    const float* x  = (const float*)d_in[0];
    const float* Wq = (const float*)d_in[1];
    const float* Wk = (const float*)d_in[2];
    const float* Wv = (const float*)d_in[3];
    const float* Wo = (const float*)d_in[4];

    cudaFuncSetAttribute(qkv16_kernel,   cudaFuncAttributeMaxDynamicSharedMemorySize, PROJ_SMEM);
    cudaFuncSetAttribute(oproj16_kernel, cudaFuncAttributeMaxDynamicSharedMemorySize, PROJ_SMEM);
    cudaFuncSetAttribute(attn_reg_kernel,cudaFuncAttributeMaxDynamicSharedMemorySize, ATT_SMEM);

    cvt_all_kernel<<<NCVT/256, 256>>>((const float2*)x,  (const float2*)Wq,
                                      (const float2*)Wk, (const float2*)Wv,
                                      (const float2*)Wo);

    qkv16_kernel<<<dim3(8, 32, 3), 256, PROJ_SMEM>>>();
    attn_reg_kernel<<<dim3(16, 16, 2), 256, ATT_SMEM>>>();
    oproj16_kernel<<<dim3(8, 32), 256, PROJ_SMEM>>>((float*)d_out);
}

// round 17
// speedup vs baseline: 1.5468x; 1.0090x over previous
#include <cuda_runtime.h>
#include <cuda_fp16.h>
#include <math.h>

#define BB 2
#define SS 2048
#define HH 16
#define DD 64
#define DIM 1024
#define MROWS (BB*SS)

// fp16 staging (device globals; no allocs allowed)
__device__ __align__(16) __half g_x16[MROWS*DIM];
__device__ __align__(16) __half g_Wq16[DIM*DIM];
__device__ __align__(16) __half g_Wk16[DIM*DIM];
__device__ __align__(16) __half g_Wv16[DIM*DIM];
__device__ __align__(16) __half g_Wo16[DIM*DIM];
__device__ __align__(16) __half g_Q16[BB*HH*SS*DD];   // (B,H,S,D), PRE-SCALED by 0.125*log2(e)
__device__ __align__(16) __half g_K16[BB*HH*SS*DD];
__device__ __align__(16) __half g_V16[BB*HH*SS*DD];
__device__ __align__(16) __half g_O16[MROWS*DIM];     // (B,S,H*D)

// ---------------- helpers ----------------
__device__ __forceinline__ void cp16(void* s, const void* g) {
    unsigned saddr = (unsigned)__cvta_generic_to_shared(s);
    asm volatile("cp.async.cg.shared.global [%0], [%1], 16;\n" :: "r"(saddr), "l"(g));
}
__device__ __forceinline__ void cp_commit() { asm volatile("cp.async.commit_group;\n"); }
template<int N> __device__ __forceinline__ void cp_wait() {
    asm volatile("cp.async.wait_group %0;\n" :: "n"(N));
}
__device__ __forceinline__ float ex2f(float x) {           // single EX2 (MUFU)
    float r;
    asm("ex2.approx.f32 %0, %1;" : "=f"(r) : "f"(x));
    return r;
}

// Single fused conversion kernel: x (2^21 half2) then Wq,Wk,Wv,Wo (2^19 half2 each).
#define NX2 (MROWS*DIM/2)         // 2097152 = 1<<21
#define NW2 (DIM*DIM/2)           // 524288  = 1<<19
#define NCVT (NX2 + 4*NW2)        // 4194304

__global__ __launch_bounds__(256) void cvt_all_kernel(
    const float2* __restrict__ x,  const float2* __restrict__ Wq,
    const float2* __restrict__ Wk, const float2* __restrict__ Wv,
    const float2* __restrict__ Wo)
{
    int i = blockIdx.x * blockDim.x + threadIdx.x;
    const float2* src;
    __half2* dst;
    int j;
    if (i < NX2) {
        src = x; dst = (__half2*)g_x16; j = i;
    } else {
        int k = i - NX2;
        int w = k >> 19;
        j = k & (NW2 - 1);
        if (w == 0)      { src = Wq; dst = (__half2*)g_Wq16; }
        else if (w == 1) { src = Wk; dst = (__half2*)g_Wk16; }
        else if (w == 2) { src = Wv; dst = (__half2*)g_Wv16; }
        else             { src = Wo; dst = (__half2*)g_Wo16; }
    }
    float2 v = src[j];
    dst[j] = __floats2half2_rn(v.x, v.y);
}

// ---------------- mma / ldmatrix PTX ----------------
__device__ __forceinline__ void ldsm4(unsigned& r0, unsigned& r1, unsigned& r2, unsigned& r3, unsigned addr) {
    asm volatile("ldmatrix.sync.aligned.m8n8.x4.shared.b16 {%0,%1,%2,%3}, [%4];\n"
                 : "=r"(r0), "=r"(r1), "=r"(r2), "=r"(r3) : "r"(addr));
}
__device__ __forceinline__ void ldsm4t(unsigned& r0, unsigned& r1, unsigned& r2, unsigned& r3, unsigned addr) {
    asm volatile("ldmatrix.sync.aligned.m8n8.x4.trans.shared.b16 {%0,%1,%2,%3}, [%4];\n"
                 : "=r"(r0), "=r"(r1), "=r"(r2), "=r"(r3) : "r"(addr));
}
__device__ __forceinline__ void mma16816(float* c, const unsigned* a, const unsigned* b) {
    asm volatile("mma.sync.aligned.m16n8k16.row.col.f32.f16.f16.f32 "
                 "{%0,%1,%2,%3}, {%4,%5,%6,%7}, {%8,%9}, {%0,%1,%2,%3};\n"
                 : "+f"(c[0]), "+f"(c[1]), "+f"(c[2]), "+f"(c[3])
                 : "r"(a[0]), "r"(a[1]), "r"(a[2]), "r"(a[3]), "r"(b[0]), "r"(b[1]));
}

// ---------------------------------------------------------------------------
// Projection GEMM (raw mma): 128x128 tile, 256 threads (8 warps, 4x2 grid),
// warp tile 32x64. KC=64, 3-stage cp.async, ONE barrier per chunk,
// BATCHED ldmatrix issues (MLP), register-direct epilogue.
// ---------------------------------------------------------------------------
#define PLA 72
#define PLB 136
#define KC  64
#define NSTG 3
#define A_ST_BYTES (128*PLA*2)     // 18432
#define B_ST_BYTES (KC*PLB*2)      // 17408
#define PROJ_SMEM (NSTG*A_ST_BYTES + NSTG*B_ST_BYTES)   // 107520

struct ProjC { float c[2][8][4]; };

__device__ __forceinline__ void proj_issue(const __half* __restrict__ X,
                                           const __half* __restrict__ W,
                                           char* smem, int m0, int n0, int k0,
                                           int buf, int tid)
{
    __half* As = (__half*)(smem + buf * A_ST_BYTES);
    __half* Bs = (__half*)(smem + NSTG * A_ST_BYTES + buf * B_ST_BYTES);
#pragma unroll
    for (int i = tid; i < 1024; i += 256) {
        int r = i >> 3, c = (i & 7) << 3;
        cp16(As + r*PLA + c, X + (size_t)(m0 + r)*DIM + k0 + c);
    }
#pragma unroll
    for (int i = tid; i < 1024; i += 256) {
        int r = i >> 4, c = (i & 15) << 3;
        cp16(Bs + r*PLB + c, W + (size_t)(k0 + r)*DIM + n0 + c);
    }
}

__device__ __forceinline__ void proj_mainloop_raw(
    const __half* __restrict__ X, const __half* __restrict__ W,
    int m0, int n0, char* smem, int tid, ProjC& P)
{
    const int wid = tid >> 5, lane = tid & 31;
    const int wm = wid >> 1, wn = wid & 1;
    const int l8 = lane & 7, g = lane >> 3;
    const int a_row = (g & 1) * 8 + l8, a_col = (g >> 1) * 8;
    const int b_row = (g & 1) * 8 + l8, b_col = (g >> 1) * 8;

#pragma unroll
    for (int i = 0; i < 2; i++)
#pragma unroll
        for (int j = 0; j < 8; j++)
#pragma unroll
            for (int t = 0; t < 4; t++) P.c[i][j][t] = 0.f;

    const unsigned smem_u = (unsigned)__cvta_generic_to_shared(smem);

    proj_issue(X, W, smem, m0, n0, 0, 0, tid); cp_commit();
    proj_issue(X, W, smem, m0, n0, KC, 1, tid); cp_commit();

    const int NIT = DIM / KC;
    for (int it = 0; it < NIT; it++) {
        int buf = it % NSTG;
        if (it + 1 < NIT) cp_wait<1>(); else cp_wait<0>();
        __syncthreads();
        if (it + 2 < NIT) { proj_issue(X, W, smem, m0, n0, (it + 2) * KC, (it + 2) % NSTG, tid); cp_commit(); }

        unsigned as_base = smem_u + buf * A_ST_BYTES;
        unsigned bs_base = smem_u + NSTG * A_ST_BYTES + buf * B_ST_BYTES;

#pragma unroll
        for (int kk = 0; kk < KC/16; kk++) {
            // batch ALL fragment loads first (6 ldsm pipelined, MLP=6)
            unsigned af[2][4];
            unsigned br[4][4];
#pragma unroll
            for (int i = 0; i < 2; i++)
                ldsm4(af[i][0], af[i][1], af[i][2], af[i][3],
                      as_base + (unsigned)(((wm*32 + i*16 + a_row)*PLA + kk*16 + a_col) * 2));
#pragma unroll
            for (int ng = 0; ng < 4; ng++)
                ldsm4t(br[ng][0], br[ng][1], br[ng][2], br[ng][3],
                       bs_base + (unsigned)(((kk*16 + b_row)*PLB + wn*64 + ng*16 + b_col) * 2));
            // then the MMA burst
#pragma unroll
            for (int ng = 0; ng < 4; ng++) {
                mma16816(P.c[0][2*ng],   af[0], br[ng]);
                mma16816(P.c[0][2*ng+1], af[0], br[ng] + 2);
                mma16816(P.c[1][2*ng],   af[1], br[ng]);
                mma16816(P.c[1][2*ng+1], af[1], br[ng] + 2);
            }
        }
    }
}

__global__ __launch_bounds__(256,2) void qkv16_kernel()
{
    extern __shared__ __align__(16) char smem[];

    const __half* W; __half* out;
    if (blockIdx.z == 0)      { W = g_Wq16; out = g_Q16; }
    else if (blockIdx.z == 1) { W = g_Wk16; out = g_K16; }
    else                      { W = g_Wv16; out = g_V16; }
    // Q gets 0.125 * log2(e): softmax runs in log2 domain (p = 2^(s'-m')).
    const float fscale = (blockIdx.z == 0) ? 0.18033688011118324f : 1.0f;

    const int tid = threadIdx.x, wid = tid >> 5, lane = tid & 31;
    const int wm = wid >> 1, wn = wid & 1;
    const int quad = lane >> 2, ql = lane & 3;
    const int m0 = blockIdx.y * 128, n0 = blockIdx.x * 128;

    ProjC P;
    proj_mainloop_raw(g_x16, W, m0, n0, smem, tid, P);

    const int bb = m0 >> 11, s0 = m0 & 2047;
    const int h = (n0 >> 6) + wn;
    __half* hb = out + (size_t)((bb << 4) + h) * SS * DD;
#pragma unroll
    for (int i = 0; i < 2; i++) {
        int ra = s0 + wm*32 + i*16 + quad;
        __half* pa_ = hb + (size_t)ra * DD;
        __half* pb_ = pa_ + 8 * DD;
#pragma unroll
        for (int j = 0; j < 8; j++) {
            int cc = j*8 + ql*2;
            *(__half2*)(pa_ + cc) = __floats2half2_rn(P.c[i][j][0]*fscale, P.c[i][j][1]*fscale);
            *(__half2*)(pb_ + cc) = __floats2half2_rn(P.c[i][j][2]*fscale, P.c[i][j][3]*fscale);
        }
    }
}

__global__ __launch_bounds__(256,2) void oproj16_kernel(float* __restrict__ C)
{
    extern __shared__ __align__(16) char smem[];
    const int tid = threadIdx.x, wid = tid >> 5, lane = tid & 31;
    const int wm = wid >> 1, wn = wid & 1;
    const int quad = lane >> 2, ql = lane & 3;
    const int m0 = blockIdx.y * 128, n0 = blockIdx.x * 128;

    ProjC P;
    proj_mainloop_raw(g_O16, g_Wo16, m0, n0, smem, tid, P);

#pragma unroll
    for (int i = 0; i < 2; i++) {
        float* pa_ = C + (size_t)(m0 + wm*32 + i*16 + quad) * DIM + n0 + wn*64;
        float* pb_ = pa_ + 8 * DIM;
#pragma unroll
        for (int j = 0; j < 8; j++) {
            int cc = j*8 + ql*2;
            *(float2*)(pa_ + cc) = make_float2(P.c[i][j][0], P.c[i][j][1]);
            *(float2*)(pb_ + cc) = make_float2(P.c[i][j][2], P.c[i][j][3]);
        }
    }
}

// ---------------------------------------------------------------------------
// Attention: register-resident FMHA, BQ=128, 8 warps, 4 KV buffers,
// 2 blocks per barrier. log2-domain softmax (Q pre-scaled by 0.125*log2e):
//   p = ex2(s'-m'), alpha = ex2(m'old-m'new). Sum inline with exp loop.
// BATCHED ldmatrix issues in S and PV loops.
// Division folded: u_j = (alpha_j/l_{j-1}) u_{j-1} + P_j V_j;  o = u_N / l_N.
// ---------------------------------------------------------------------------
#define LDH 72
#define A_QS   0
#define A_KS   18432
#define A_VS   (18432 + 4*9216)
#define ATT_SMEM (18432 + 8*9216)          // 92160

__global__ __launch_bounds__(256,2) void attn_reg_kernel()
{
    extern __shared__ __align__(16) char smem[];
    __half* Qs = (__half*)(smem + A_QS);

    const int tid = threadIdx.x, wid = tid >> 5, lane = tid & 31;
    const int qb = blockIdx.x, h = blockIdx.y, b = blockIdx.z;
    const int r0 = wid * 16;
    const int l8 = lane & 7, g = lane >> 3;
    const int quad = lane >> 2, ql = lane & 3;

    const __half* Qg  = g_Q16 + ((size_t)((b << 4) + h) * SS + qb * 128) * DD;
    const __half* Kg0 = g_K16 + (size_t)((b << 4) + h) * SS * DD;
    const __half* Vg0 = g_V16 + (size_t)((b << 4) + h) * SS * DD;

    auto issueKV = [&](int j) {
        int buf = j & 3;
        __half* Ks = (__half*)(smem + A_KS + buf * 9216);
        __half* Vs = (__half*)(smem + A_VS + buf * 9216);
        const __half* Kg = Kg0 + (size_t)j * (64*DD);
        const __half* Vg = Vg0 + (size_t)j * (64*DD);
#pragma unroll
        for (int i = tid; i < 512; i += 256) {
            int r = i >> 3, c = (i & 7) << 3;
            cp16(Ks + r*LDH + c, Kg + r*DD + c);
            cp16(Vs + r*LDH + c, Vg + r*DD + c);
        }
    };

    issueKV(0); issueKV(1); cp_commit();

#pragma unroll
    for (int i = tid; i < 1024; i += 256) {
        int r = i >> 3, c = (i & 7) << 3;
        *(uint4*)(Qs + r*LDH + c) = *(const uint4*)(Qg + r*DD + c);
    }
    __syncthreads();

    unsigned qs_base = (unsigned)__cvta_generic_to_shared(Qs);
    unsigned qf[4][4];
    {
        int qrow = r0 + (g & 1) * 8 + l8;
        int qcol = (g >> 1) * 8;
#pragma unroll
        for (int kt = 0; kt < 4; kt++) {
            ldsm4(qf[kt][0], qf[kt][1], qf[kt][2], qf[kt][3],
                  qs_base + (qrow*LDH + kt*16 + qcol) * 2);
        }
    }

    const int k_row = (g >> 1) * 8 + l8, k_col = (g & 1) * 8;
    const int v_row = (g & 1) * 8 + l8,  v_col = (g >> 1) * 8;
    const unsigned smem_base = (unsigned)__cvta_generic_to_shared(smem);

    float u[8][4];
#pragma unroll
    for (int nt = 0; nt < 8; nt++) {
#pragma unroll
        for (int t = 0; t < 4; t++) u[nt][t] = 0.f;
    }

    float mrun_a = -INFINITY, mrun_b = -INFINITY, lrun_a = 0.f, lrun_b = 0.f;

    auto process_block = [&](int j) {
        int buf = j & 3;
        unsigned ks_base = smem_base + A_KS + buf * 9216;
        unsigned vs_base = smem_base + A_VS + buf * 9216;

        // ---- S' = Q' @ K^T (log2 domain); batched K-frag loads per kt ----
        float sacc[8][4];
#pragma unroll
        for (int nt = 0; nt < 8; nt++) {
#pragma unroll
            for (int t = 0; t < 4; t++) sacc[nt][t] = 0.f;
        }

#pragma unroll
        for (int kt = 0; kt < 4; kt++) {
            unsigned kr[4][4];
#pragma unroll
            for (int ng = 0; ng < 4; ng++)
                ldsm4(kr[ng][0], kr[ng][1], kr[ng][2], kr[ng][3],
                      ks_base + ((ng*16 + k_row)*LDH + kt*16 + k_col) * 2);
#pragma unroll
            for (int ng = 0; ng < 4; ng++) {
                mma16816(sacc[2*ng],   qf[kt], kr[ng]);
                mma16816(sacc[2*ng+1], qf[kt], kr[ng] + 2);
            }
        }

        // ---- online softmax (rows quad, quad+8); p = 2^(s'-m') ----
        float mxa = -INFINITY, mxb = -INFINITY;
#pragma unroll
        for (int nt = 0; nt < 8; nt++) {
            mxa = fmaxf(mxa, fmaxf(sacc[nt][0], sacc[nt][1]));
            mxb = fmaxf(mxb, fmaxf(sacc[nt][2], sacc[nt][3]));
        }
        mxa = fmaxf(mxa, __shfl_xor_sync(0xffffffffu, mxa, 1));
        mxa = fmaxf(mxa, __shfl_xor_sync(0xffffffffu, mxa, 2));
        mxb = fmaxf(mxb, __shfl_xor_sync(0xffffffffu, mxb, 1));
        mxb = fmaxf(mxb, __shfl_xor_sync(0xffffffffu, mxb, 2));

        float mna = fmaxf(mrun_a, mxa), mnb = fmaxf(mrun_b, mxb);
        float suma = 0.f, sumb = 0.f;
#pragma unroll
        for (int nt = 0; nt < 8; nt++) {
            sacc[nt][0] = ex2f(sacc[nt][0] - mna);
            sacc[nt][1] = ex2f(sacc[nt][1] - mna);
            sacc[nt][2] = ex2f(sacc[nt][2] - mnb);
            sacc[nt][3] = ex2f(sacc[nt][3] - mnb);
            suma += sacc[nt][0] + sacc[nt][1];
            sumb += sacc[nt][2] + sacc[nt][3];
        }
        suma += __shfl_xor_sync(0xffffffffu, suma, 1);
        suma += __shfl_xor_sync(0xffffffffu, suma, 2);
        sumb += __shfl_xor_sync(0xffffffffu, sumb, 1);
        sumb += __shfl_xor_sync(0xffffffffu, sumb, 2);

        float alpha_a = ex2f(mrun_a - mna), alpha_b = ex2f(mrun_b - mnb);
        float beta_a = (lrun_a > 0.f) ? (alpha_a / lrun_a) : 0.f;
        float beta_b = (lrun_b > 0.f) ? (alpha_b / lrun_b) : 0.f;
        lrun_a = alpha_a * lrun_a + suma;
        lrun_b = alpha_b * lrun_b + sumb;
        mrun_a = mna; mrun_b = mnb;

        // ---- pack P (fp16) into A-fragments ----
        unsigned pa[4][4];
#pragma unroll
        for (int kt = 0; kt < 4; kt++) {
            __half2 h0 = __floats2half2_rn(sacc[2*kt][0],   sacc[2*kt][1]);
            __half2 h1 = __floats2half2_rn(sacc[2*kt][2],   sacc[2*kt][3]);
            __half2 h2 = __floats2half2_rn(sacc[2*kt+1][0], sacc[2*kt+1][1]);
            __half2 h3 = __floats2half2_rn(sacc[2*kt+1][2], sacc[2*kt+1][3]);
            pa[kt][0] = *(unsigned*)&h0;
            pa[kt][1] = *(unsigned*)&h1;
            pa[kt][2] = *(unsigned*)&h2;
            pa[kt][3] = *(unsigned*)&h3;
        }

        // ---- u = beta*u + P@V ; batched V-frag loads per kt ----
#pragma unroll
        for (int nt = 0; nt < 8; nt++) {
            u[nt][0] *= beta_a; u[nt][1] *= beta_a;
            u[nt][2] *= beta_b; u[nt][3] *= beta_b;
        }
#pragma unroll
        for (int kt = 0; kt < 4; kt++) {
            unsigned vr[4][4];
#pragma unroll
            for (int dg = 0; dg < 4; dg++)
                ldsm4t(vr[dg][0], vr[dg][1], vr[dg][2], vr[dg][3],
                       vs_base + ((kt*16 + v_row)*LDH + dg*16 + v_col) * 2);
#pragma unroll
            for (int dg = 0; dg < 4; dg++) {
                mma16816(u[2*dg],   pa[kt], vr[dg]);
                mma16816(u[2*dg+1], pa[kt], vr[dg] + 2);
            }
        }
    };

    for (int gi = 0; gi < SS/128; gi++) {
        cp_wait<0>();
        __syncthreads();
        if (gi + 1 < SS/128) { issueKV(2*gi + 2); issueKV(2*gi + 3); cp_commit(); }
        process_block(2*gi);
        process_block(2*gi + 1);
    }

    float inva = 1.f / lrun_a, invb = 1.f / lrun_b;
    {
        int row_a = qb*128 + r0 + quad;
        __half* base_a = g_O16 + ((size_t)(b * SS + row_a)) * DIM + h * DD;
        __half* base_b = base_a + (size_t)8 * DIM;
#pragma unroll
        for (int nt = 0; nt < 8; nt++) {
            int c = nt*8 + ql*2;
            *(__half2*)(base_a + c) = __floats2half2_rn(u[nt][0] * inva, u[nt][1] * inva);
            *(__half2*)(base_b + c) = __floats2half2_rn(u[nt][2] * invb, u[nt][3] * invb);
        }
    }
}

// ---------------------------------------------------------------------------
extern "C" void kernel_launch(void* const* d_in, const int* in_sizes, int n_in,
                              void* d_out, int out_size)
{
    const float* x  = (const float*)d_in[0];
    const float* Wq = (const float*)d_in[1];
    const float* Wk = (const float*)d_in[2];
    const float* Wv = (const float*)d_in[3];
    const float* Wo = (const float*)d_in[4];

    cudaFuncSetAttribute(qkv16_kernel,   cudaFuncAttributeMaxDynamicSharedMemorySize, PROJ_SMEM);
    cudaFuncSetAttribute(oproj16_kernel, cudaFuncAttributeMaxDynamicSharedMemorySize, PROJ_SMEM);
    cudaFuncSetAttribute(attn_reg_kernel,cudaFuncAttributeMaxDynamicSharedMemorySize, ATT_SMEM);

    cvt_all_kernel<<<NCVT/256, 256>>>((const float2*)x,  (const float2*)Wq,
                                      (const float2*)Wk, (const float2*)Wv,
                                      (const float2*)Wo);

    qkv16_kernel<<<dim3(8, 32, 3), 256, PROJ_SMEM>>>();
    attn_reg_kernel<<<dim3(16, 16, 2), 256, ATT_SMEM>>>();
    oproj16_kernel<<<dim3(8, 32), 256, PROJ_SMEM>>>((float*)d_out);
}